// round 3
// baseline (speedup 1.0000x reference)
#include <cuda_runtime.h>
#include <math.h>

#define BB 16
#define DD 8
#define FF 2
#define EE 10
#define NP 512
#define NPAIR 36
#define LOG2E 1.4426950408889634f

// ---------------- scratch (device globals; no allocation allowed) ----------
__device__ float g_Sigma[BB][EE][EE];
__device__ float g_nu[BB][NP][EE];
__device__ float g_P[BB][DD][NP][EE];
__device__ float g_logk[BB][DD][NP];
__device__ float g_mu_delta[BB][DD];
__device__ float g_V[BB][DD][EE];
__device__ float g_Tl[BB][NPAIR][NP][EE];   // (Pa @ S) * log2(e)
__device__ float g_gv[BB][NPAIR][NP];       // beta_a * exp(c_a - 0.25 logdetR)
__device__ float g_hv[BB][NPAIR][NP];       // beta_d * exp(c_b - 0.25 logdetR)
__device__ float g_g2[BB][NPAIR][NP];       // exp(c_a - 0.25 logdetR)
__device__ float g_h2[BB][NPAIR][NP];       // exp(c_b - 0.25 logdetR)
__device__ float g_EDD[BB][DD][DD];
__device__ float g_tr[BB][DD];

__device__ __forceinline__ float ex2f(float x) {
    float y;
    asm("ex2.approx.ftz.f32 %0, %1;" : "=f"(y) : "f"(x));
    return y;
}

__device__ __forceinline__ void pair_of(int p, int &a, int &d) {
    int aa = 0;
    while (p >= DD - aa) { p -= DD - aa; aa++; }
    a = aa; d = aa + p;
}

// block-wide sum; valid in all threads on return
__device__ float blockReduceSum(float v, float* sred) {
    const unsigned full = 0xffffffffu;
    #pragma unroll
    for (int o = 16; o > 0; o >>= 1) v += __shfl_down_sync(full, v, o);
    int t = threadIdx.x, warp = t >> 5, lane = t & 31;
    int nw = blockDim.x >> 5;
    if (lane == 0) sred[warp] = v;
    __syncthreads();
    float r = (t < nw) ? sred[t] : 0.f;
    if (warp == 0) {
        #pragma unroll
        for (int o = 16; o > 0; o >>= 1) r += __shfl_down_sync(full, r, o);
        if (lane == 0) sred[0] = r;
    }
    __syncthreads();
    float out = sred[0];
    __syncthreads();
    return out;
}

// Gauss-Jordan: solve M X = RHS in shared memory (RHS in X on entry),
// X <- M^{-1} * X, logdet(M) in *ldout. Warp 0 cooperates, lanes = columns.
// Matrices here are strongly diagonally dominant (I + small, or diag(ell^2) + small),
// so no pivoting is needed.
__device__ void gj_solve10(float (*M)[EE + 1], float (*X)[EE + 1], float* ldout) {
    int t = threadIdx.x;
    if (t < 32) {
        int lane = t;
        float ld = 0.f;
        for (int k = 0; k < EE; k++) {
            float piv = M[k][k];
            ld += logf(fabsf(piv));
            float inv = 1.f / piv;
            __syncwarp();
            if (lane < EE) { M[k][lane] *= inv; X[k][lane] *= inv; }
            __syncwarp();
            for (int r = 0; r < EE; r++) {
                if (r == k) continue;
                float fac = M[r][k];
                __syncwarp();
                if (lane < EE) {
                    M[r][lane] -= fac * M[k][lane];
                    X[r][lane] -= fac * X[k][lane];
                }
                __syncwarp();
            }
        }
        if (lane == 0) *ldout = ld;
    }
    __syncthreads();
}

// ---------------- kernel 1: mu, Sigma, nu, P, logk -------------------------
__global__ void __launch_bounds__(NP)
k_prep(const float* __restrict__ obs_mean, const float* __restrict__ obs_var,
       const float* __restrict__ action_mean, const float* __restrict__ action_var,
       const float* __restrict__ cross_cov, const float* __restrict__ X_train,
       const float* __restrict__ ell, const float* __restrict__ alpha_sq) {
    int b = blockIdx.x, t = threadIdx.x;
    __shared__ float smu[EE];
    __shared__ float siLam[DD][EE];
    __shared__ float slal[DD];
    if (t < DD) smu[t] = obs_mean[b * DD + t];
    else if (t < EE) smu[t] = action_mean[b * FF + (t - DD)];
    if (t < DD * EE) {
        int d = t / EE, e = t % EE;
        float l = ell[d * EE + e];
        siLam[d][e] = 1.f / (l * l);
    }
    if (t >= 128 && t < 128 + DD) slal[t - 128] = logf(alpha_sq[t - 128]);
    if (t >= 256 && t < 256 + EE * EE) {
        int q = t - 256, e = q / EE, f = q % EE;
        float v;
        if (e < DD && f < DD)      v = obs_var[b * DD * DD + e * DD + f];
        else if (e < DD)           v = cross_cov[b * DD * FF + e * FF + (f - DD)];
        else if (f < DD)           v = cross_cov[b * DD * FF + f * FF + (e - DD)];
        else                       v = action_var[b * FF * FF + (e - DD) * FF + (f - DD)];
        g_Sigma[b][e][f] = v;
    }
    __syncthreads();
    int n = t;  // 512 threads == NP
    float nu[EE];
    #pragma unroll
    for (int e = 0; e < EE; e++) {
        nu[e] = X_train[n * EE + e] - smu[e];
        g_nu[b][n][e] = nu[e];
    }
    for (int d = 0; d < DD; d++) {
        float s = 0.f;
        #pragma unroll
        for (int e = 0; e < EE; e++) {
            float p = nu[e] * siLam[d][e];
            g_P[b][d][n][e] = p;
            s = fmaf(nu[e] * nu[e], siLam[d][e], s);
        }
        g_logk[b][d][n] = slal[d] - 0.5f * s;
    }
}

// ---------------- kernel 2: per (b,d) -- Ainv, q, mu_delta, w, V -----------
__global__ void __launch_bounds__(NP)
k_perdim(const float* __restrict__ ell, const float* __restrict__ alpha_sq,
         const float* __restrict__ beta) {
    int bd = blockIdx.x;
    int b = bd / DD, d = bd % DD;
    int t = threadIdx.x;
    __shared__ float sM[EE][EE + 1], sX[EE][EE + 1];
    __shared__ float sld;
    __shared__ float sred[32];
    if (t < EE * EE) {
        int e = t / EE, f = t % EE;
        float diag = (e == f) ? (ell[d * EE + e] * ell[d * EE + e]) : 0.f;
        sM[e][f] = g_Sigma[b][e][f] + diag;
        sX[e][f] = (e == f) ? 1.f : 0.f;
    }
    __syncthreads();
    gj_solve10(sM, sX, &sld);  // sX = Ainv, sld = logdetA

    float ldl = 0.f;
    #pragma unroll
    for (int e = 0; e < EE; e++) { float l = ell[d * EE + e]; ldl += logf(l * l); }

    int n = t;
    float nu[EE];
    #pragma unroll
    for (int e = 0; e < EE; e++) nu[e] = g_nu[b][n][e];
    float quad = 0.f;
    #pragma unroll
    for (int e = 0; e < EE; e++) {
        float acc = 0.f;
        #pragma unroll
        for (int f = 0; f < EE; f++) acc = fmaf(sX[e][f], nu[f], acc);
        quad = fmaf(nu[e], acc, quad);
    }
    float q = alpha_sq[d] * __expf(0.5f * (ldl - sld) - 0.5f * quad);
    float bq = beta[d * NP + n] * q;

    float md = blockReduceSum(bq, sred);
    float wreg[EE];
    for (int e = 0; e < EE; e++) wreg[e] = blockReduceSum(bq * nu[e], sred);

    if (t == 0) {
        g_mu_delta[b][d] = md;
        float u[EE];
        for (int e = 0; e < EE; e++) {
            float a = 0.f;
            for (int f = 0; f < EE; f++) a = fmaf(sX[e][f], wreg[f], a);
            u[e] = a;
        }
        for (int e = 0; e < EE; e++) {
            float a = 0.f;
            for (int f = 0; f < EE; f++) a = fmaf(g_Sigma[b][e][f], u[f], a);
            g_V[b][d][e] = a;
        }
    }
}

// ---------------- kernel 3: per (b,pair) -- S, logdetR, T, g, h ------------
__global__ void __launch_bounds__(NP)
k_pairprep(const float* __restrict__ ell, const float* __restrict__ beta) {
    int bp = blockIdx.x;
    int b = bp / NPAIR, p = bp % NPAIR;
    int a, d;
    pair_of(p, a, d);
    int t = threadIdx.x;
    __shared__ float sM[EE][EE + 1], sX[EE][EE + 1];
    __shared__ float sld;
    if (t < EE * EE) {
        int e = t / EE, f = t % EE;
        float la = ell[a * EE + f], ldd = ell[d * EE + f];
        float ils = 1.f / (la * la) + 1.f / (ldd * ldd);
        sM[e][f] = g_Sigma[b][e][f] * ils + ((e == f) ? 1.f : 0.f);
        sX[e][f] = g_Sigma[b][e][f];
    }
    __syncthreads();
    gj_solve10(sM, sX, &sld);  // sX = S = R^{-1} Sigma, sld = logdetR

    int n = t;
    float Pv[EE], Tv[EE];
    // a-side
    #pragma unroll
    for (int e = 0; e < EE; e++) Pv[e] = g_P[b][a][n][e];
    #pragma unroll
    for (int e = 0; e < EE; e++) {
        float acc = 0.f;
        #pragma unroll
        for (int f = 0; f < EE; f++) acc = fmaf(Pv[f], sX[f][e], acc);
        Tv[e] = acc;
    }
    float da = 0.f;
    #pragma unroll
    for (int e = 0; e < EE; e++) da = fmaf(Tv[e], Pv[e], da);
    #pragma unroll
    for (int e = 0; e < EE; e++) g_Tl[b][p][n][e] = Tv[e] * LOG2E;
    float g2 = __expf(g_logk[b][a][n] + 0.5f * da - 0.25f * sld);
    g_g2[b][p][n] = g2;
    g_gv[b][p][n] = beta[a * NP + n] * g2;
    // d-side
    #pragma unroll
    for (int e = 0; e < EE; e++) Pv[e] = g_P[b][d][n][e];
    #pragma unroll
    for (int e = 0; e < EE; e++) {
        float acc = 0.f;
        #pragma unroll
        for (int f = 0; f < EE; f++) acc = fmaf(Pv[f], sX[f][e], acc);
        Tv[e] = acc;
    }
    float db = 0.f;
    #pragma unroll
    for (int e = 0; e < EE; e++) db = fmaf(Tv[e], Pv[e], db);
    float h2 = __expf(g_logk[b][d][n] + 0.5f * db - 0.25f * sld);
    g_h2[b][p][n] = h2;
    g_hv[b][p][n] = beta[d * NP + n] * h2;
}

// ---------------- kernel 4: the big 512x512 contractions -------------------
__global__ void __launch_bounds__(256) k_main(const float* __restrict__ invK) {
    int bp = blockIdx.x;
    int b = bp / NPAIR, p = bp % NPAIR;
    int a, d;
    pair_of(p, a, d);
    const bool diag = (a == d);
    int t = threadIdx.x, tx = t & 15, ty = t >> 4;

    __shared__ float sT[64][EE + 1];
    __shared__ float sP[64][EE + 1];
    __shared__ float sg[64], sh[64], sg2[64], sh2[64];
    __shared__ float sred[32];

    const float* Krow = invK + (size_t)a * NP * NP;

    float acc = 0.f, tacc = 0.f;

    for (int i0 = 0; i0 < NP; i0 += 64) {
        for (int k = t; k < 64 * EE; k += 256) {
            int r = k / EE, e = k % EE;
            sT[r][e] = g_Tl[b][p][i0 + r][e];
        }
        for (int k = t; k < 64; k += 256) {
            sg[k] = g_gv[b][p][i0 + k];
            sg2[k] = g_g2[b][p][i0 + k];
        }
        __syncthreads();

        float Treg[4][EE], gr[4], g2r[4];
        #pragma unroll
        for (int ii = 0; ii < 4; ii++) {
            int r = ty * 4 + ii;
            #pragma unroll
            for (int e = 0; e < EE; e++) Treg[ii][e] = sT[r][e];
            gr[ii] = sg[r];
            g2r[ii] = sg2[r];
        }

        for (int j0 = 0; j0 < NP; j0 += 64) {
            for (int k = t; k < 64 * EE; k += 256) {
                int r = k / EE, e = k % EE;
                sP[r][e] = g_P[b][d][j0 + r][e];
            }
            for (int k = t; k < 64; k += 256) {
                sh[k] = g_hv[b][p][j0 + k];
                sh2[k] = g_h2[b][p][j0 + k];
            }
            __syncthreads();

            float Preg[4][EE], hr[4], h2r[4];
            #pragma unroll
            for (int jj = 0; jj < 4; jj++) {
                int r = tx * 4 + jj;
                #pragma unroll
                for (int e = 0; e < EE; e++) Preg[jj][e] = sP[r][e];
                hr[jj] = sh[r];
                h2r[jj] = sh2[r];
            }

            if (diag) {
                #pragma unroll
                for (int ii = 0; ii < 4; ii++) {
                    const float4 kv4 = *(const float4*)(Krow + (size_t)(i0 + ty * 4 + ii) * NP + j0 + tx * 4);
                    float kvv[4] = {kv4.x, kv4.y, kv4.z, kv4.w};
                    float r1 = 0.f, r2 = 0.f;
                    #pragma unroll
                    for (int jj = 0; jj < 4; jj++) {
                        float m = 0.f;
                        #pragma unroll
                        for (int e = 0; e < EE; e++) m = fmaf(Treg[ii][e], Preg[jj][e], m);
                        float e2 = ex2f(m);
                        r1 = fmaf(e2, hr[jj], r1);
                        r2 = fmaf(e2 * h2r[jj], kvv[jj], r2);
                    }
                    acc = fmaf(gr[ii], r1, acc);
                    tacc = fmaf(g2r[ii], r2, tacc);
                }
            } else {
                #pragma unroll
                for (int ii = 0; ii < 4; ii++) {
                    float r1 = 0.f;
                    #pragma unroll
                    for (int jj = 0; jj < 4; jj++) {
                        float m = 0.f;
                        #pragma unroll
                        for (int e = 0; e < EE; e++) m = fmaf(Treg[ii][e], Preg[jj][e], m);
                        float e2 = ex2f(m);
                        r1 = fmaf(e2, hr[jj], r1);
                    }
                    acc = fmaf(gr[ii], r1, acc);
                }
            }
            __syncthreads();
        }
    }

    float tot = blockReduceSum(acc, sred);
    if (diag) {
        float tt = blockReduceSum(tacc, sred);
        if (t == 0) g_tr[b][a] = tt;
    }
    if (t == 0) {
        g_EDD[b][a][d] = tot;
        g_EDD[b][d][a] = tot;
    }
}

// ---------------- kernel 5: final assembly ---------------------------------
__global__ void __launch_bounds__(64)
k_final(const float* __restrict__ obs_mean, const float* __restrict__ obs_var,
        const float* __restrict__ alpha_sq, const float* __restrict__ sigma_sq_eps,
        float* __restrict__ out) {
    int b = blockIdx.x, t = threadIdx.x;
    if (t < DD) {
        out[b * DD + t] = obs_mean[b * DD + t] + g_mu_delta[b][t];
    }
    if (t < DD * DD) {
        int i = t / DD, j = t % DD;
        float sd = g_EDD[b][i][j] - g_mu_delta[b][i] * g_mu_delta[b][j];
        if (i == j) sd += alpha_sq[i] - g_tr[b][i] + sigma_sq_eps[i];
        float v = obs_var[b * DD * DD + i * DD + j] + sd + g_V[b][j][i] + g_V[b][i][j];
        out[BB * DD + b * DD * DD + i * DD + j] = v;
    }
}

extern "C" void kernel_launch(void* const* d_in, const int* in_sizes, int n_in,
                              void* d_out, int out_size) {
    const float* obs_mean     = (const float*)d_in[0];
    const float* obs_var      = (const float*)d_in[1];
    const float* action_mean  = (const float*)d_in[2];
    const float* action_var   = (const float*)d_in[3];
    const float* cross_cov    = (const float*)d_in[4];
    const float* X_train      = (const float*)d_in[5];
    const float* ell          = (const float*)d_in[6];
    const float* alpha_sq     = (const float*)d_in[7];
    const float* sigma_sq_eps = (const float*)d_in[8];
    const float* beta         = (const float*)d_in[9];
    const float* inv_K        = (const float*)d_in[10];
    float* out = (float*)d_out;

    k_prep<<<BB, NP>>>(obs_mean, obs_var, action_mean, action_var, cross_cov,
                       X_train, ell, alpha_sq);
    k_perdim<<<BB * DD, NP>>>(ell, alpha_sq, beta);
    k_pairprep<<<BB * NPAIR, NP>>>(ell, beta);
    k_main<<<BB * NPAIR, 256>>>(inv_K);
    k_final<<<BB, 64>>>(obs_mean, obs_var, alpha_sq, sigma_sq_eps, out);
}

// round 7
// speedup vs baseline: 1.0656x; 1.0656x over previous
#include <cuda_runtime.h>
#include <math.h>

#define BB 16
#define DD 8
#define FF 2
#define EE 10
#define NP 512
#define NPAIR 36
#define LOG2E 1.4426950408889634f

// ---------------- scratch (device globals; no allocation allowed) ----------
__device__ float g_Sigma[BB][EE][EE];
__device__ float g_nu[BB][NP][EE];
__device__ float g_P[BB][DD][NP][EE];
__device__ float g_logk[BB][DD][NP];
__device__ float g_mu_delta[BB][DD];
__device__ float g_V[BB][DD][EE];
__device__ float g_Tl[BB][NPAIR][NP][EE];   // (Pa @ S) * log2(e)
__device__ float g_gv[BB][NPAIR][NP];       // beta_a * exp(c_a - 0.25 logdetR)
__device__ float g_hv[BB][NPAIR][NP];       // beta_d * exp(c_b - 0.25 logdetR)
__device__ float g_g2[BB][NPAIR][NP];       // exp(c_a - 0.25 logdetR)
__device__ float g_h2[BB][NPAIR][NP];       // exp(c_b - 0.25 logdetR)
__device__ float g_EDD[BB][DD][DD];
__device__ float g_tr[BB][DD];

__device__ __forceinline__ float ex2f(float x) {
    float y;
    asm("ex2.approx.ftz.f32 %0, %1;" : "=f"(y) : "f"(x));
    return y;
}

__device__ __forceinline__ void pair_of(int p, int &a, int &d) {
    int aa = 0;
    while (p >= DD - aa) { p -= DD - aa; aa++; }
    a = aa; d = aa + p;
}

// block-wide sum; valid in all threads on return
__device__ float blockReduceSum(float v, float* sred) {
    const unsigned full = 0xffffffffu;
    #pragma unroll
    for (int o = 16; o > 0; o >>= 1) v += __shfl_down_sync(full, v, o);
    int t = threadIdx.x, warp = t >> 5, lane = t & 31;
    int nw = blockDim.x >> 5;
    if (lane == 0) sred[warp] = v;
    __syncthreads();
    float r = (t < nw) ? sred[t] : 0.f;
    if (warp == 0) {
        #pragma unroll
        for (int o = 16; o > 0; o >>= 1) r += __shfl_down_sync(full, r, o);
        if (lane == 0) sred[0] = r;
    }
    __syncthreads();
    float out = sred[0];
    __syncthreads();
    return out;
}

// Gauss-Jordan: solve M X = RHS in shared memory (RHS in X on entry),
// X <- M^{-1} * X, logdet(M) in *ldout. Warp 0 cooperates, lanes = columns.
__device__ void gj_solve10(float (*M)[EE + 1], float (*X)[EE + 1], float* ldout) {
    int t = threadIdx.x;
    if (t < 32) {
        int lane = t;
        float ld = 0.f;
        for (int k = 0; k < EE; k++) {
            float piv = M[k][k];
            ld += logf(fabsf(piv));
            float inv = 1.f / piv;
            __syncwarp();
            if (lane < EE) { M[k][lane] *= inv; X[k][lane] *= inv; }
            __syncwarp();
            for (int r = 0; r < EE; r++) {
                if (r == k) continue;
                float fac = M[r][k];
                __syncwarp();
                if (lane < EE) {
                    M[r][lane] -= fac * M[k][lane];
                    X[r][lane] -= fac * X[k][lane];
                }
                __syncwarp();
            }
        }
        if (lane == 0) *ldout = ld;
    }
    __syncthreads();
}

// ---------------- kernel 1: mu, Sigma, nu, P, logk -------------------------
__global__ void __launch_bounds__(NP)
k_prep(const float* __restrict__ obs_mean, const float* __restrict__ obs_var,
       const float* __restrict__ action_mean, const float* __restrict__ action_var,
       const float* __restrict__ cross_cov, const float* __restrict__ X_train,
       const float* __restrict__ ell, const float* __restrict__ alpha_sq) {
    int b = blockIdx.x, t = threadIdx.x;
    __shared__ float smu[EE];
    __shared__ float siLam[DD][EE];
    __shared__ float slal[DD];
    if (t < DD) smu[t] = obs_mean[b * DD + t];
    else if (t < EE) smu[t] = action_mean[b * FF + (t - DD)];
    if (t < DD * EE) {
        int d = t / EE, e = t % EE;
        float l = ell[d * EE + e];
        siLam[d][e] = 1.f / (l * l);
    }
    if (t >= 128 && t < 128 + DD) slal[t - 128] = logf(alpha_sq[t - 128]);
    if (t >= 256 && t < 256 + EE * EE) {
        int q = t - 256, e = q / EE, f = q % EE;
        float v;
        if (e < DD && f < DD)      v = obs_var[b * DD * DD + e * DD + f];
        else if (e < DD)           v = cross_cov[b * DD * FF + e * FF + (f - DD)];
        else if (f < DD)           v = cross_cov[b * DD * FF + f * FF + (e - DD)];
        else                       v = action_var[b * FF * FF + (e - DD) * FF + (f - DD)];
        g_Sigma[b][e][f] = v;
    }
    __syncthreads();
    int n = t;  // 512 threads == NP
    float nu[EE];
    #pragma unroll
    for (int e = 0; e < EE; e++) {
        nu[e] = X_train[n * EE + e] - smu[e];
        g_nu[b][n][e] = nu[e];
    }
    for (int d = 0; d < DD; d++) {
        float s = 0.f;
        #pragma unroll
        for (int e = 0; e < EE; e++) {
            float p = nu[e] * siLam[d][e];
            g_P[b][d][n][e] = p;
            s = fmaf(nu[e] * nu[e], siLam[d][e], s);
        }
        g_logk[b][d][n] = slal[d] - 0.5f * s;
    }
}

// ---------------- kernel 2: per (b,d) -- Ainv, q, mu_delta, w, V -----------
__global__ void __launch_bounds__(NP)
k_perdim(const float* __restrict__ ell, const float* __restrict__ alpha_sq,
         const float* __restrict__ beta) {
    int bd = blockIdx.x;
    int b = bd / DD, d = bd % DD;
    int t = threadIdx.x;
    __shared__ float sM[EE][EE + 1], sX[EE][EE + 1];
    __shared__ float sld;
    __shared__ float sred[32];
    if (t < EE * EE) {
        int e = t / EE, f = t % EE;
        float diag = (e == f) ? (ell[d * EE + e] * ell[d * EE + e]) : 0.f;
        sM[e][f] = g_Sigma[b][e][f] + diag;
        sX[e][f] = (e == f) ? 1.f : 0.f;
    }
    __syncthreads();
    gj_solve10(sM, sX, &sld);  // sX = Ainv, sld = logdetA

    float ldl = 0.f;
    #pragma unroll
    for (int e = 0; e < EE; e++) { float l = ell[d * EE + e]; ldl += logf(l * l); }

    int n = t;
    float nu[EE];
    #pragma unroll
    for (int e = 0; e < EE; e++) nu[e] = g_nu[b][n][e];
    float quad = 0.f;
    #pragma unroll
    for (int e = 0; e < EE; e++) {
        float acc = 0.f;
        #pragma unroll
        for (int f = 0; f < EE; f++) acc = fmaf(sX[e][f], nu[f], acc);
        quad = fmaf(nu[e], acc, quad);
    }
    float q = alpha_sq[d] * __expf(0.5f * (ldl - sld) - 0.5f * quad);
    float bq = beta[d * NP + n] * q;

    float md = blockReduceSum(bq, sred);
    float wreg[EE];
    for (int e = 0; e < EE; e++) wreg[e] = blockReduceSum(bq * nu[e], sred);

    if (t == 0) {
        g_mu_delta[b][d] = md;
        float u[EE];
        for (int e = 0; e < EE; e++) {
            float a = 0.f;
            for (int f = 0; f < EE; f++) a = fmaf(sX[e][f], wreg[f], a);
            u[e] = a;
        }
        for (int e = 0; e < EE; e++) {
            float a = 0.f;
            for (int f = 0; f < EE; f++) a = fmaf(g_Sigma[b][e][f], u[f], a);
            g_V[b][d][e] = a;
        }
    }
}

// ---------------- kernel 3: per (b,pair) -- S, logdetR, T, g, h ------------
__global__ void __launch_bounds__(NP)
k_pairprep(const float* __restrict__ ell, const float* __restrict__ beta) {
    int bp = blockIdx.x;
    int b = bp / NPAIR, p = bp % NPAIR;
    int a, d;
    pair_of(p, a, d);
    int t = threadIdx.x;
    __shared__ float sM[EE][EE + 1], sX[EE][EE + 1];
    __shared__ float sld;
    if (t < EE * EE) {
        int e = t / EE, f = t % EE;
        float la = ell[a * EE + f], ldd = ell[d * EE + f];
        float ils = 1.f / (la * la) + 1.f / (ldd * ldd);
        sM[e][f] = g_Sigma[b][e][f] * ils + ((e == f) ? 1.f : 0.f);
        sX[e][f] = g_Sigma[b][e][f];
    }
    __syncthreads();
    gj_solve10(sM, sX, &sld);  // sX = S = R^{-1} Sigma, sld = logdetR

    int n = t;
    float Pv[EE], Tv[EE];
    // a-side
    #pragma unroll
    for (int e = 0; e < EE; e++) Pv[e] = g_P[b][a][n][e];
    #pragma unroll
    for (int e = 0; e < EE; e++) {
        float acc = 0.f;
        #pragma unroll
        for (int f = 0; f < EE; f++) acc = fmaf(Pv[f], sX[f][e], acc);
        Tv[e] = acc;
    }
    float da = 0.f;
    #pragma unroll
    for (int e = 0; e < EE; e++) da = fmaf(Tv[e], Pv[e], da);
    #pragma unroll
    for (int e = 0; e < EE; e++) g_Tl[b][p][n][e] = Tv[e] * LOG2E;
    float g2 = __expf(g_logk[b][a][n] + 0.5f * da - 0.25f * sld);
    g_g2[b][p][n] = g2;
    g_gv[b][p][n] = beta[a * NP + n] * g2;
    // d-side
    #pragma unroll
    for (int e = 0; e < EE; e++) Pv[e] = g_P[b][d][n][e];
    #pragma unroll
    for (int e = 0; e < EE; e++) {
        float acc = 0.f;
        #pragma unroll
        for (int f = 0; f < EE; f++) acc = fmaf(Pv[f], sX[f][e], acc);
        Tv[e] = acc;
    }
    float db = 0.f;
    #pragma unroll
    for (int e = 0; e < EE; e++) db = fmaf(Tv[e], Pv[e], db);
    float h2 = __expf(g_logk[b][d][n] + 0.5f * db - 0.25f * sld);
    g_h2[b][p][n] = h2;
    g_hv[b][p][n] = beta[d * NP + n] * h2;
}

// ---------------- kernel 4: the big 512x512 contractions -------------------
// Register-lean: cache T rows (4x10) in regs, stream P rows from smem per jj.
__global__ void __launch_bounds__(256) k_main(const float* __restrict__ invK) {
    int bp = blockIdx.x;
    int b = bp / NPAIR, p = bp % NPAIR;
    int a, d;
    pair_of(p, a, d);
    const bool diag = (a == d);
    int t = threadIdx.x, tx = t & 15, ty = t >> 4;

    __shared__ float sT[64][EE + 1];
    __shared__ float sP[64][EE + 1];
    __shared__ float sg[64], sh[64], sg2[64], sh2[64];
    __shared__ float sred[32];

    const float* Krow = invK + (size_t)a * NP * NP;

    float acc = 0.f, tacc = 0.f;

    for (int i0 = 0; i0 < NP; i0 += 64) {
        for (int k = t; k < 64 * EE; k += 256) {
            int r = k / EE, e = k % EE;
            sT[r][e] = g_Tl[b][p][i0 + r][e];
        }
        for (int k = t; k < 64; k += 256) {
            sg[k] = g_gv[b][p][i0 + k];
            sg2[k] = g_g2[b][p][i0 + k];
        }
        __syncthreads();

        float Treg[4][EE];
        #pragma unroll
        for (int ii = 0; ii < 4; ii++) {
            int r = ty * 4 + ii;
            #pragma unroll
            for (int e = 0; e < EE; e++) Treg[ii][e] = sT[r][e];
        }

        // accumulate over ALL j for this i-tile; scale by g at the end
        float racc[4] = {0.f, 0.f, 0.f, 0.f};
        float t2acc[4] = {0.f, 0.f, 0.f, 0.f};

        for (int j0 = 0; j0 < NP; j0 += 64) {
            for (int k = t; k < 64 * EE; k += 256) {
                int r = k / EE, e = k % EE;
                sP[r][e] = g_P[b][d][j0 + r][e];
            }
            for (int k = t; k < 64; k += 256) {
                sh[k] = g_hv[b][p][j0 + k];
                sh2[k] = g_h2[b][p][j0 + k];
            }
            __syncthreads();

            if (diag) {
                // prefetch invK 4x4 patch for this thread's micro-tile
                float kvv[4][4];
                #pragma unroll
                for (int ii = 0; ii < 4; ii++) {
                    const float4 kv4 = *(const float4*)(Krow + (size_t)(i0 + ty * 4 + ii) * NP + j0 + tx * 4);
                    kvv[ii][0] = kv4.x; kvv[ii][1] = kv4.y; kvv[ii][2] = kv4.z; kvv[ii][3] = kv4.w;
                }
                #pragma unroll
                for (int jj = 0; jj < 4; jj++) {
                    int r = tx * 4 + jj;
                    float Pv[EE];
                    #pragma unroll
                    for (int e = 0; e < EE; e++) Pv[e] = sP[r][e];
                    float hj = sh[r], h2j = sh2[r];
                    float m0 = 0.f, m1 = 0.f, m2 = 0.f, m3 = 0.f;
                    #pragma unroll
                    for (int e = 0; e < EE; e++) {
                        m0 = fmaf(Treg[0][e], Pv[e], m0);
                        m1 = fmaf(Treg[1][e], Pv[e], m1);
                        m2 = fmaf(Treg[2][e], Pv[e], m2);
                        m3 = fmaf(Treg[3][e], Pv[e], m3);
                    }
                    float e0 = ex2f(m0), e1 = ex2f(m1), e2 = ex2f(m2), e3 = ex2f(m3);
                    racc[0] = fmaf(e0, hj, racc[0]);
                    racc[1] = fmaf(e1, hj, racc[1]);
                    racc[2] = fmaf(e2, hj, racc[2]);
                    racc[3] = fmaf(e3, hj, racc[3]);
                    t2acc[0] = fmaf(e0 * h2j, kvv[0][jj], t2acc[0]);
                    t2acc[1] = fmaf(e1 * h2j, kvv[1][jj], t2acc[1]);
                    t2acc[2] = fmaf(e2 * h2j, kvv[2][jj], t2acc[2]);
                    t2acc[3] = fmaf(e3 * h2j, kvv[3][jj], t2acc[3]);
                }
            } else {
                #pragma unroll
                for (int jj = 0; jj < 4; jj++) {
                    int r = tx * 4 + jj;
                    float Pv[EE];
                    #pragma unroll
                    for (int e = 0; e < EE; e++) Pv[e] = sP[r][e];
                    float hj = sh[r];
                    float m0 = 0.f, m1 = 0.f, m2 = 0.f, m3 = 0.f;
                    #pragma unroll
                    for (int e = 0; e < EE; e++) {
                        m0 = fmaf(Treg[0][e], Pv[e], m0);
                        m1 = fmaf(Treg[1][e], Pv[e], m1);
                        m2 = fmaf(Treg[2][e], Pv[e], m2);
                        m3 = fmaf(Treg[3][e], Pv[e], m3);
                    }
                    racc[0] = fmaf(ex2f(m0), hj, racc[0]);
                    racc[1] = fmaf(ex2f(m1), hj, racc[1]);
                    racc[2] = fmaf(ex2f(m2), hj, racc[2]);
                    racc[3] = fmaf(ex2f(m3), hj, racc[3]);
                }
            }
            __syncthreads();
        }

        #pragma unroll
        for (int ii = 0; ii < 4; ii++) {
            int r = ty * 4 + ii;
            acc = fmaf(sg[r], racc[ii], acc);
            if (diag) tacc = fmaf(sg2[r], t2acc[ii], tacc);
        }
        __syncthreads();
    }

    float tot = blockReduceSum(acc, sred);
    if (diag) {
        float tt = blockReduceSum(tacc, sred);
        if (t == 0) g_tr[b][a] = tt;
    }
    if (t == 0) {
        g_EDD[b][a][d] = tot;
        g_EDD[b][d][a] = tot;
    }
}

// ---------------- kernel 5: final assembly ---------------------------------
__global__ void __launch_bounds__(64)
k_final(const float* __restrict__ obs_mean, const float* __restrict__ obs_var,
        const float* __restrict__ alpha_sq, const float* __restrict__ sigma_sq_eps,
        float* __restrict__ out) {
    int b = blockIdx.x, t = threadIdx.x;
    if (t < DD) {
        out[b * DD + t] = obs_mean[b * DD + t] + g_mu_delta[b][t];
    }
    if (t < DD * DD) {
        int i = t / DD, j = t % DD;
        float sd = g_EDD[b][i][j] - g_mu_delta[b][i] * g_mu_delta[b][j];
        if (i == j) sd += alpha_sq[i] - g_tr[b][i] + sigma_sq_eps[i];
        float v = obs_var[b * DD * DD + i * DD + j] + sd + g_V[b][j][i] + g_V[b][i][j];
        out[BB * DD + b * DD * DD + i * DD + j] = v;
    }
}

extern "C" void kernel_launch(void* const* d_in, const int* in_sizes, int n_in,
                              void* d_out, int out_size) {
    const float* obs_mean     = (const float*)d_in[0];
    const float* obs_var      = (const float*)d_in[1];
    const float* action_mean  = (const float*)d_in[2];
    const float* action_var   = (const float*)d_in[3];
    const float* cross_cov    = (const float*)d_in[4];
    const float* X_train      = (const float*)d_in[5];
    const float* ell          = (const float*)d_in[6];
    const float* alpha_sq     = (const float*)d_in[7];
    const float* sigma_sq_eps = (const float*)d_in[8];
    const float* beta         = (const float*)d_in[9];
    const float* inv_K        = (const float*)d_in[10];
    float* out = (float*)d_out;

    k_prep<<<BB, NP>>>(obs_mean, obs_var, action_mean, action_var, cross_cov,
                       X_train, ell, alpha_sq);
    k_perdim<<<BB * DD, NP>>>(ell, alpha_sq, beta);
    k_pairprep<<<BB * NPAIR, NP>>>(ell, beta);
    k_main<<<BB * NPAIR, 256>>>(inv_K);
    k_final<<<BB, 64>>>(obs_mean, obs_var, alpha_sq, sigma_sq_eps, out);
}